// round 1
// baseline (speedup 1.0000x reference)
#include <cuda_runtime.h>
#include <cuda_bf16.h>
#include <math_constants.h>

// Problem shape (fixed by reference): B=8, S=2048, D=Dv=1024, fp32.
// r = softmax( (q @ k) * 0.1 , axis=-1) @ v
//   q: [B, S, D] row-major
//   k: [B, D, S] row-major  (so q@k is a plain NN GEMM)
//   v: [B, S, Dv] row-major
// Strategy (round 1 baseline): 3 kernels
//   1) batched SGEMM  scores = 0.1 * q @ k     -> __device__ scratch (134 MB)
//   2) row softmax over scores (rows of length S=2048), in place
//   3) batched SGEMM  out = scores @ v

#define ATT_B  8
#define ATT_S  2048
#define ATT_D  1024

// 8 * 2048 * 2048 floats = 128 MiB scratch (static __device__ is allowed)
__device__ float g_scores[(size_t)ATT_B * ATT_S * ATT_S];

// ---------------------------------------------------------------------------
// Tiled batched SGEMM (NN, row-major): C = alpha * A(MxK) * B(KxN)
// BM=BN=128, BK=16, 256 threads, 8x8 per-thread micro-tile.
// ---------------------------------------------------------------------------
#define BM 128
#define BN 128
#define BK 16
#define TM 8
#define TN 8

__global__ __launch_bounds__(256) void sgemm_nn(
    const float* __restrict__ A, const float* __restrict__ Bm,
    float* __restrict__ C,
    int M, int N, int K, float alpha,
    long long strideA, long long strideB, long long strideC)
{
    const int b = blockIdx.z;
    A  += (long long)b * strideA;
    Bm += (long long)b * strideB;
    C  += (long long)b * strideC;

    __shared__ float As[BK][BM + 4];   // A tile stored transposed (k-major)
    __shared__ float Bs[BK][BN];

    const int tid  = threadIdx.x;           // 0..255
    const int row0 = blockIdx.y * BM;
    const int col0 = blockIdx.x * BN;

    const int tr = (tid / 16) * TM;         // 0..120
    const int tc = (tid % 16) * TN;         // 0..120

    float acc[TM][TN];
    #pragma unroll
    for (int i = 0; i < TM; i++)
        #pragma unroll
        for (int j = 0; j < TN; j++)
            acc[i][j] = 0.0f;

    for (int k0 = 0; k0 < K; k0 += BK) {
        // Load A tile: 128 rows x 16 cols = 512 float4, 2 per thread.
        #pragma unroll
        for (int i = 0; i < 2; i++) {
            int r  = (tid >> 2) + i * 64;       // 0..127
            int c4 = (tid & 3) * 4;             // 0,4,8,12
            float4 t = *(const float4*)(A + (long long)(row0 + r) * K + k0 + c4);
            As[c4 + 0][r] = t.x;
            As[c4 + 1][r] = t.y;
            As[c4 + 2][r] = t.z;
            As[c4 + 3][r] = t.w;
        }
        // Load B tile: 16 rows x 128 cols = 512 float4, 2 per thread.
        #pragma unroll
        for (int i = 0; i < 2; i++) {
            int r  = (tid >> 5) + i * 8;        // 0..15
            int c4 = (tid & 31) * 4;            // 0..124
            *(float4*)&Bs[r][c4] =
                *(const float4*)(Bm + (long long)(k0 + r) * N + col0 + c4);
        }
        __syncthreads();

        #pragma unroll
        for (int kk = 0; kk < BK; kk++) {
            float a[TM], bb[TN];
            float4 a0 = *(const float4*)&As[kk][tr];
            float4 a1 = *(const float4*)&As[kk][tr + 4];
            a[0]=a0.x; a[1]=a0.y; a[2]=a0.z; a[3]=a0.w;
            a[4]=a1.x; a[5]=a1.y; a[6]=a1.z; a[7]=a1.w;
            float4 b0 = *(const float4*)&Bs[kk][tc];
            float4 b1 = *(const float4*)&Bs[kk][tc + 4];
            bb[0]=b0.x; bb[1]=b0.y; bb[2]=b0.z; bb[3]=b0.w;
            bb[4]=b1.x; bb[5]=b1.y; bb[6]=b1.z; bb[7]=b1.w;
            #pragma unroll
            for (int i = 0; i < TM; i++)
                #pragma unroll
                for (int j = 0; j < TN; j++)
                    acc[i][j] = fmaf(a[i], bb[j], acc[i][j]);
        }
        __syncthreads();
    }

    #pragma unroll
    for (int i = 0; i < TM; i++) {
        #pragma unroll
        for (int j = 0; j < TN; j += 4) {
            float4 t;
            t.x = alpha * acc[i][j + 0];
            t.y = alpha * acc[i][j + 1];
            t.z = alpha * acc[i][j + 2];
            t.w = alpha * acc[i][j + 3];
            *(float4*)(C + (long long)(row0 + tr + i) * N + col0 + tc + j) = t;
        }
    }
}

// ---------------------------------------------------------------------------
// Row softmax, in place. One block (256 threads) per row of length S=2048.
// Each thread owns 8 elements.
// ---------------------------------------------------------------------------
__global__ __launch_bounds__(256) void softmax_rows(float* __restrict__ scores)
{
    const long long row = blockIdx.x;
    float* p = scores + row * (long long)ATT_S;
    const int tid = threadIdx.x;

    float v[8];
    float m = -CUDART_INF_F;
    #pragma unroll
    for (int i = 0; i < 8; i++) {
        v[i] = p[tid + i * 256];
        m = fmaxf(m, v[i]);
    }

    __shared__ float red[8];

    // block max
    #pragma unroll
    for (int o = 16; o > 0; o >>= 1)
        m = fmaxf(m, __shfl_xor_sync(0xffffffffu, m, o));
    if ((tid & 31) == 0) red[tid >> 5] = m;
    __syncthreads();
    float bm = red[0];
    #pragma unroll
    for (int i = 1; i < 8; i++) bm = fmaxf(bm, red[i]);
    __syncthreads();

    // exp + block sum
    float s = 0.0f;
    #pragma unroll
    for (int i = 0; i < 8; i++) {
        v[i] = __expf(v[i] - bm);
        s += v[i];
    }
    #pragma unroll
    for (int o = 16; o > 0; o >>= 1)
        s += __shfl_xor_sync(0xffffffffu, s, o);
    if ((tid & 31) == 0) red[tid >> 5] = s;
    __syncthreads();
    float total = 0.0f;
    #pragma unroll
    for (int i = 0; i < 8; i++) total += red[i];

    float inv = 1.0f / total;
    #pragma unroll
    for (int i = 0; i < 8; i++)
        p[tid + i * 256] = v[i] * inv;
}

// ---------------------------------------------------------------------------
// Launch
// ---------------------------------------------------------------------------
extern "C" void kernel_launch(void* const* d_in, const int* in_sizes, int n_in,
                              void* d_out, int out_size)
{
    const float* q = (const float*)d_in[0];   // [B, S, D]
    const float* k = (const float*)d_in[1];   // [B, D, S]
    const float* v = (const float*)d_in[2];   // [B, S, D]
    float* out = (float*)d_out;               // [B, S, D]

    float* scores;
    cudaGetSymbolAddress((void**)&scores, g_scores);

    const int B = ATT_B, S = ATT_S, D = ATT_D;

    // 1) scores = 0.1 * q @ k    (M=S, N=S, K=D)
    {
        dim3 grid(S / BN, S / BM, B);
        sgemm_nn<<<grid, 256>>>(q, k, scores,
                                S, S, D, 0.1f,
                                (long long)S * D, (long long)D * S, (long long)S * S);
    }

    // 2) softmax over rows of scores
    {
        softmax_rows<<<B * S, 256>>>(scores);
    }

    // 3) out = scores @ v        (M=S, N=D, K=S)
    {
        dim3 grid(D / BN, S / BM, B);
        sgemm_nn<<<grid, 256>>>(scores, v, out,
                                S, D, S, 1.0f,
                                (long long)S * S, (long long)S * D, (long long)S * D);
    }
}

// round 2
// speedup vs baseline: 1.6173x; 1.6173x over previous
#include <cuda_runtime.h>
#include <cuda_bf16.h>
#include <math_constants.h>

// r = softmax( (q @ k) * 0.1 , axis=-1) @ v
// B=8, S=2048, D=Dv=1024, fp32.
// Round 2: inner product loop uses packed fma.rn.f32x2 (SASS FFMA2) for 2x
// fp32 FMA throughput on the fma pipe.

#define ATT_B  8
#define ATT_S  2048
#define ATT_D  1024

__device__ float g_scores[(size_t)ATT_B * ATT_S * ATT_S];

#define BM 128
#define BN 128
#define BK 16
#define TM 8
#define TN 8

typedef unsigned long long u64;

__device__ __forceinline__ u64 pack_dup(float x) {
    u64 r;
    asm("mov.b64 %0, {%1, %1};" : "=l"(r) : "f"(x));
    return r;
}
__device__ __forceinline__ u64 fma2(u64 a, u64 b, u64 c) {
    u64 d;
    asm("fma.rn.f32x2 %0, %1, %2, %3;" : "=l"(d) : "l"(a), "l"(b), "l"(c));
    return d;
}
__device__ __forceinline__ float2 unpack2(u64 p) {
    float lo, hi;
    asm("mov.b64 {%0, %1}, %2;" : "=f"(lo), "=f"(hi) : "l"(p));
    return make_float2(lo, hi);
}

// ---------------------------------------------------------------------------
// Tiled batched SGEMM (NN, row-major): C = alpha * A(MxK) * B(KxN)
// ---------------------------------------------------------------------------
__global__ __launch_bounds__(256) void sgemm_nn(
    const float* __restrict__ A, const float* __restrict__ Bm,
    float* __restrict__ C,
    int M, int N, int K, float alpha,
    long long strideA, long long strideB, long long strideC)
{
    const int b = blockIdx.z;
    A  += (long long)b * strideA;
    Bm += (long long)b * strideB;
    C  += (long long)b * strideC;

    __shared__ float As[BK][BM + 4];   // A tile transposed (k-major)
    __shared__ __align__(8) float Bs[BK][BN];

    const int tid  = threadIdx.x;           // 0..255
    const int row0 = blockIdx.y * BM;
    const int col0 = blockIdx.x * BN;

    const int tr = (tid / 16) * TM;         // 0..120
    const int tc = (tid % 16) * TN;         // 0..120

    u64 acc2[TM][TN / 2];                    // packed f32x2 accumulators
    #pragma unroll
    for (int i = 0; i < TM; i++)
        #pragma unroll
        for (int j = 0; j < TN / 2; j++)
            acc2[i][j] = 0ull;

    for (int k0 = 0; k0 < K; k0 += BK) {
        // Load A tile: 128 rows x 16 cols, stored transposed in smem.
        #pragma unroll
        for (int i = 0; i < 2; i++) {
            int r  = (tid >> 2) + i * 64;       // 0..127
            int c4 = (tid & 3) * 4;             // 0,4,8,12
            float4 t = *(const float4*)(A + (long long)(row0 + r) * K + k0 + c4);
            As[c4 + 0][r] = t.x;
            As[c4 + 1][r] = t.y;
            As[c4 + 2][r] = t.z;
            As[c4 + 3][r] = t.w;
        }
        // Load B tile: 16 rows x 128 cols.
        #pragma unroll
        for (int i = 0; i < 2; i++) {
            int r  = (tid >> 5) + i * 8;        // 0..15
            int c4 = (tid & 31) * 4;            // 0..124
            *(float4*)&Bs[r][c4] =
                *(const float4*)(Bm + (long long)(k0 + r) * N + col0 + c4);
        }
        __syncthreads();

        #pragma unroll
        for (int kk = 0; kk < BK; kk++) {
            // a values: duplicated into both halves of packed regs
            float4 a0 = *(const float4*)&As[kk][tr];
            float4 a1 = *(const float4*)&As[kk][tr + 4];
            u64 a2[TM];
            a2[0] = pack_dup(a0.x); a2[1] = pack_dup(a0.y);
            a2[2] = pack_dup(a0.z); a2[3] = pack_dup(a0.w);
            a2[4] = pack_dup(a1.x); a2[5] = pack_dup(a1.y);
            a2[6] = pack_dup(a1.z); a2[7] = pack_dup(a1.w);
            // b pairs: natural adjacent packing, loaded as 64-bit
            const u64* bp = (const u64*)&Bs[kk][tc];
            u64 b2[TN / 2];
            b2[0] = bp[0]; b2[1] = bp[1]; b2[2] = bp[2]; b2[3] = bp[3];

            #pragma unroll
            for (int i = 0; i < TM; i++)
                #pragma unroll
                for (int j = 0; j < TN / 2; j++)
                    acc2[i][j] = fma2(a2[i], b2[j], acc2[i][j]);
        }
        __syncthreads();
    }

    #pragma unroll
    for (int i = 0; i < TM; i++) {
        float4 t0, t1;
        float2 p;
        p = unpack2(acc2[i][0]); t0.x = alpha * p.x; t0.y = alpha * p.y;
        p = unpack2(acc2[i][1]); t0.z = alpha * p.x; t0.w = alpha * p.y;
        p = unpack2(acc2[i][2]); t1.x = alpha * p.x; t1.y = alpha * p.y;
        p = unpack2(acc2[i][3]); t1.z = alpha * p.x; t1.w = alpha * p.y;
        *(float4*)(C + (long long)(row0 + tr + i) * N + col0 + tc + 0) = t0;
        *(float4*)(C + (long long)(row0 + tr + i) * N + col0 + tc + 4) = t1;
    }
}

// ---------------------------------------------------------------------------
// Row softmax, in place. One block (256 threads) per row of length S=2048.
// ---------------------------------------------------------------------------
__global__ __launch_bounds__(256) void softmax_rows(float* __restrict__ scores)
{
    const long long row = blockIdx.x;
    float* p = scores + row * (long long)ATT_S;
    const int tid = threadIdx.x;

    float v[8];
    float m = -CUDART_INF_F;
    #pragma unroll
    for (int i = 0; i < 8; i++) {
        v[i] = p[tid + i * 256];
        m = fmaxf(m, v[i]);
    }

    __shared__ float red[8];

    #pragma unroll
    for (int o = 16; o > 0; o >>= 1)
        m = fmaxf(m, __shfl_xor_sync(0xffffffffu, m, o));
    if ((tid & 31) == 0) red[tid >> 5] = m;
    __syncthreads();
    float bm = red[0];
    #pragma unroll
    for (int i = 1; i < 8; i++) bm = fmaxf(bm, red[i]);
    __syncthreads();

    float s = 0.0f;
    #pragma unroll
    for (int i = 0; i < 8; i++) {
        v[i] = __expf(v[i] - bm);
        s += v[i];
    }
    #pragma unroll
    for (int o = 16; o > 0; o >>= 1)
        s += __shfl_xor_sync(0xffffffffu, s, o);
    if ((tid & 31) == 0) red[tid >> 5] = s;
    __syncthreads();
    float total = 0.0f;
    #pragma unroll
    for (int i = 0; i < 8; i++) total += red[i];

    float inv = 1.0f / total;
    #pragma unroll
    for (int i = 0; i < 8; i++)
        p[tid + i * 256] = v[i] * inv;
}

// ---------------------------------------------------------------------------
extern "C" void kernel_launch(void* const* d_in, const int* in_sizes, int n_in,
                              void* d_out, int out_size)
{
    const float* q = (const float*)d_in[0];   // [B, S, D]
    const float* k = (const float*)d_in[1];   // [B, D, S]
    const float* v = (const float*)d_in[2];   // [B, S, D]
    float* out = (float*)d_out;               // [B, S, D]

    float* scores;
    cudaGetSymbolAddress((void**)&scores, g_scores);

    const int B = ATT_B, S = ATT_S, D = ATT_D;

    {   // scores = 0.1 * q @ k    (M=S, N=S, K=D)
        dim3 grid(S / BN, S / BM, B);
        sgemm_nn<<<grid, 256>>>(q, k, scores,
                                S, S, D, 0.1f,
                                (long long)S * D, (long long)D * S, (long long)S * S);
    }
    {   // softmax rows
        softmax_rows<<<B * S, 256>>>(scores);
    }
    {   // out = scores @ v        (M=S, N=D, K=S)
        dim3 grid(D / BN, S / BM, B);
        sgemm_nn<<<grid, 256>>>(scores, v, out,
                                S, D, S, 1.0f,
                                (long long)S * S, (long long)S * D, (long long)S * D);
    }
}

// round 4
// speedup vs baseline: 2.7361x; 1.6918x over previous
#include <cuda_runtime.h>
#include <math_constants.h>
#include <cstdint>

typedef unsigned int u32;
typedef unsigned long long u64;

// r = softmax( (q @ k) * 0.1 , -1) @ v ; B=8, S=2048, D=Dv=1024, fp32.
// Round 4: tcgen05 tf32 GEMMs, with arch-feature guards so the compute_103
// (non-'a') PTX stage compiles a stub while the sm_103a cubin has real code.

#if defined(__CUDA_ARCH_FEAT_SM103_ALL) || defined(__CUDA_ARCH_FEAT_SM100_ALL) || \
    defined(__CUDA_ARCH_SPECIFIC__)
#define HAS_TCGEN05 1
#else
#define HAS_TCGEN05 0
#endif

#define ATT_B 8
#define ATT_S 2048
#define ATT_D 1024

__device__ float g_scores[(size_t)ATT_B * ATT_S * ATT_S];

// ---------------- PTX helpers (only referenced under HAS_TCGEN05) ----------
__device__ __forceinline__ u32 smem_u32(const void* p) {
    u32 a;
    asm("{ .reg .u64 t; cvta.to.shared.u64 t, %1; cvt.u32.u64 %0, t; }"
        : "=r"(a) : "l"(p));
    return a;
}
__device__ __forceinline__ u32 elect1() {
    u32 p;
    asm volatile("{ .reg .pred p; elect.sync _|p, 0xFFFFFFFF; selp.b32 %0,1,0,p; }"
                 : "=r"(p));
    return p;
}
__device__ __forceinline__ u32 cvt_tf32(float x) {
    u32 r;
    asm("cvt.rn.tf32.f32 %0, %1;" : "=r"(r) : "f"(x));
    return r;
}
__device__ __forceinline__ void mbar_init(u32 mbar, u32 cnt) {
    asm volatile("mbarrier.init.shared.b64 [%0], %1;" :: "r"(mbar), "r"(cnt) : "memory");
}
__device__ __forceinline__ void mbar_wait(u32 mbar, u32 parity) {
    asm volatile(
        "{ .reg .pred P;\n"
        "L%=: mbarrier.try_wait.parity.acquire.cta.shared::cta.b64 P, [%0], %1, 0x989680;\n"
        "@P bra D%=;\n"
        "bra L%=;\n"
        "D%=: }\n"
        :: "r"(mbar), "r"(parity) : "memory");
}

#if HAS_TCGEN05
__device__ __forceinline__ void tmem_alloc(u32 smem_dst, u32 ncols) {
    asm volatile("tcgen05.alloc.cta_group::1.sync.aligned.shared::cta.b32 [%0], %1;"
                 :: "r"(smem_dst), "r"(ncols) : "memory");
}
__device__ __forceinline__ void tmem_relinquish() {
    asm volatile("tcgen05.relinquish_alloc_permit.cta_group::1.sync.aligned;");
}
__device__ __forceinline__ void tmem_dealloc(u32 tmem, u32 ncols) {
    asm volatile("tcgen05.dealloc.cta_group::1.sync.aligned.b32 %0, %1;"
                 :: "r"(tmem), "r"(ncols));
}
__device__ __forceinline__ void mma_tf32_ss(u32 d_tmem, u64 ad, u64 bd, u32 idesc, u32 en) {
    asm volatile(
        "{ .reg .pred p; setp.ne.u32 p, %4, 0;\n"
        "tcgen05.mma.cta_group::1.kind::tf32 [%0], %1, %2, %3, {%5,%5,%5,%5}, p;\n }"
        :: "r"(d_tmem), "l"(ad), "l"(bd), "r"(idesc), "r"(en), "r"(0u) : "memory");
}
__device__ __forceinline__ void mma_commit(u32 mbar) {
    asm volatile(
        "tcgen05.commit.cta_group::1.mbarrier::arrive::one.shared::cluster.b64 [%0];"
        :: "r"(mbar) : "memory");
}
__device__ __forceinline__ void tc_fence_after() {
    asm volatile("tcgen05.fence::after_thread_sync;" ::: "memory");
}
__device__ __forceinline__ void tmem_ld32(u32* r, u32 tmem) {
    asm volatile(
        "tcgen05.ld.sync.aligned.32x32b.x32.b32 "
        "{%0,%1,%2,%3,%4,%5,%6,%7,%8,%9,%10,%11,%12,%13,%14,%15,"
        "%16,%17,%18,%19,%20,%21,%22,%23,%24,%25,%26,%27,%28,%29,%30,%31}, [%32];"
        : "=r"(r[0]), "=r"(r[1]), "=r"(r[2]), "=r"(r[3]),
          "=r"(r[4]), "=r"(r[5]), "=r"(r[6]), "=r"(r[7]),
          "=r"(r[8]), "=r"(r[9]), "=r"(r[10]), "=r"(r[11]),
          "=r"(r[12]), "=r"(r[13]), "=r"(r[14]), "=r"(r[15]),
          "=r"(r[16]), "=r"(r[17]), "=r"(r[18]), "=r"(r[19]),
          "=r"(r[20]), "=r"(r[21]), "=r"(r[22]), "=r"(r[23]),
          "=r"(r[24]), "=r"(r[25]), "=r"(r[26]), "=r"(r[27]),
          "=r"(r[28]), "=r"(r[29]), "=r"(r[30]), "=r"(r[31])
        : "r"(tmem));
}
__device__ __forceinline__ void tmem_wait_ld() {
    asm volatile("tcgen05.wait::ld.sync.aligned;" ::: "memory");
}
#endif  // HAS_TCGEN05

__device__ __forceinline__ void fence_async_proxy() {
    asm volatile("fence.proxy.async.shared::cta;" ::: "memory");
}

#define SW128(o) ((o) ^ (((o) >> 3) & 0x70))

// SW128 K-major SMEM descriptor: layout=2, version=1, SBO=64, LBO=1
static constexpr u64 DESC_BASE =
    (2ull << 61) | (1ull << 46) | (64ull << 32) | (1ull << 16);
__device__ __forceinline__ u64 mk_desc(u32 addr) {
    return DESC_BASE | ((u64)(addr >> 4) & 0x3FFF);
}

// idesc kind::tf32: dtype=F32(1)<<4, atype=TF32(2)<<7, btype=TF32(2)<<10,
// N/8<<17, M/16<<24.  M=128, N=128.
static constexpr u32 IDESC_TF32 =
    (1u << 4) | (2u << 7) | (2u << 10) | ((128u / 8) << 17) | ((128u / 16) << 24);

// Tile config: CTA computes 128x128 of C; K-tiles of 32 fp32 (=128B SW128 rows).
#define TILE_BYTES 16384      // 128 rows * 128 B
#define TK 32
// Dynamic smem: 1024 ctrl + up to 1024 alignment pad + 4 tiles
#define SMEM_DYN (1024 + 1024 + 4 * TILE_BYTES)

// ---------------------------------------------------------------------------
// tcgen05 tf32 batched GEMM:  C[M,N] = alpha * A[M,K] @ B[K,N]
// A row-major (lda=K), B row-major (ldb=N), C row-major (ldc=N).
// ---------------------------------------------------------------------------
__global__ __launch_bounds__(128) void gemm_tf32(
    const float* __restrict__ A, const float* __restrict__ Bg,
    float* __restrict__ C, int K, int lda, int ldb, int ldc, float alpha,
    long long strideA, long long strideB, long long strideC)
{
#if HAS_TCGEN05
    extern __shared__ char smem[];
    const u32 smem_base = smem_u32(smem);
    // 1024-aligned tile region
    const u32 pad = ((smem_base + 1024 + 1023) & ~1023u) - smem_base;
    char* tiles = smem + pad;
    const u32 tiles_addr = smem_base + pad;

    const int tid = threadIdx.x;
    const int wid = tid >> 5;
    const int lid = tid & 31;

    const int b = blockIdx.z;
    A  += (long long)b * strideA;
    Bg += (long long)b * strideB;
    C  += (long long)b * strideC;

    const int row0 = blockIdx.y * 128;
    const int col0 = blockIdx.x * 128;

    const u32 mbar[2] = { smem_base + 8, smem_base + 16 };
    const u32 mbarF   = smem_base + 24;

    if (tid == 0) {
        mbar_init(mbar[0], 1);
        mbar_init(mbar[1], 1);
        mbar_init(mbarF, 1);
    }
    if (wid == 0) {
        tmem_alloc(smem_base + 0, 128);
        tmem_relinquish();
    }
    __syncthreads();
    u32 tmem;
    asm volatile("ld.shared.b32 %0, [%1];" : "=r"(tmem) : "r"(smem_base + 0));

    const int KT = K / TK;
    int ph0 = 0, ph1 = 0;

    for (int kt = 0; kt < KT; kt++) {
        const int buf = kt & 1;
        if (kt >= 2) {
            if (buf == 0) { mbar_wait(mbar[0], ph0); ph0 ^= 1; }
            else          { mbar_wait(mbar[1], ph1); ph1 ^= 1; }
        }
        const int k0 = kt * TK;
        char* At = tiles + buf * TILE_BYTES;
        char* Bt = tiles + (2 + buf) * TILE_BYTES;

        // ---- A tile: 128 rows x 32 fp32, K-major, SW128, tf32-rounded ----
        {
            const int c16 = tid & 7;            // 16B chunk within 128B row
            int r = tid >> 3;                   // base row
            #pragma unroll
            for (int i = 0; i < 8; i++, r += 16) {
                float4 t = *(const float4*)(A + (long long)(row0 + r) * lda + k0 + c16 * 4);
                uint4 u;
                u.x = cvt_tf32(t.x); u.y = cvt_tf32(t.y);
                u.z = cvt_tf32(t.z); u.w = cvt_tf32(t.w);
                *(uint4*)(At + SW128(r * 128 + c16 * 16)) = u;
            }
        }
        // ---- B tile transposed: Bsm[n][k] = Bg[k0+k][col0+n], n=tid ----
        {
            const int n = tid;
            const float* bp = Bg + (long long)k0 * ldb + col0 + n;
            #pragma unroll
            for (int k4 = 0; k4 < 8; k4++) {
                uint4 u;
                u.x = cvt_tf32(bp[(k4 * 4 + 0) * (long long)ldb]);
                u.y = cvt_tf32(bp[(k4 * 4 + 1) * (long long)ldb]);
                u.z = cvt_tf32(bp[(k4 * 4 + 2) * (long long)ldb]);
                u.w = cvt_tf32(bp[(k4 * 4 + 3) * (long long)ldb]);
                *(uint4*)(Bt + SW128(n * 128 + k4 * 16)) = u;
            }
        }
        fence_async_proxy();
        __syncthreads();

        if (wid == 0) {
            if (elect1()) {
                const u32 Aaddr = tiles_addr + buf * TILE_BYTES;
                const u32 Baddr = tiles_addr + (2 + buf) * TILE_BYTES;
                const u64 ad = mk_desc(Aaddr);
                const u64 bd = mk_desc(Baddr);
                #pragma unroll
                for (int sub = 0; sub < 4; sub++) {
                    // +2 (= 32B in 16B units) per K=8 tf32 step
                    mma_tf32_ss(tmem, ad + sub * 2, bd + sub * 2, IDESC_TF32,
                                (kt | sub) != 0);
                }
                mma_commit(mbar[buf]);
            }
        }
    }

    // final drain
    if (wid == 0 && elect1()) mma_commit(mbarF);
    mbar_wait(mbarF, 0);
    tc_fence_after();

    // epilogue: warp w owns rows w*32..w*32+31; read 4 chunks of 32 cols
    const int grow = row0 + wid * 32 + lid;
    float* crow = C + (long long)grow * ldc + col0;
    #pragma unroll
    for (int cb = 0; cb < 4; cb++) {
        u32 r[32];
        tmem_ld32(r, tmem + cb * 32);
        tmem_wait_ld();
        #pragma unroll
        for (int j = 0; j < 32; j += 4) {
            float4 t;
            t.x = alpha * __uint_as_float(r[j + 0]);
            t.y = alpha * __uint_as_float(r[j + 1]);
            t.z = alpha * __uint_as_float(r[j + 2]);
            t.w = alpha * __uint_as_float(r[j + 3]);
            *(float4*)(crow + cb * 32 + j) = t;
        }
    }

    __syncthreads();
    if (wid == 0) tmem_dealloc(tmem, 128);
#endif  // HAS_TCGEN05
}

// ---------------------------------------------------------------------------
// Row softmax, in place (rows of length 2048), 256 threads/row.
// ---------------------------------------------------------------------------
__global__ __launch_bounds__(256) void softmax_rows(float* __restrict__ scores)
{
    const long long row = blockIdx.x;
    float* p = scores + row * (long long)ATT_S;
    const int tid = threadIdx.x;

    float v[8];
    float m = -CUDART_INF_F;
    #pragma unroll
    for (int i = 0; i < 8; i++) {
        v[i] = p[tid + i * 256];
        m = fmaxf(m, v[i]);
    }
    __shared__ float red[8];
    #pragma unroll
    for (int o = 16; o > 0; o >>= 1)
        m = fmaxf(m, __shfl_xor_sync(0xffffffffu, m, o));
    if ((tid & 31) == 0) red[tid >> 5] = m;
    __syncthreads();
    float bm = red[0];
    #pragma unroll
    for (int i = 1; i < 8; i++) bm = fmaxf(bm, red[i]);
    __syncthreads();

    float s = 0.0f;
    #pragma unroll
    for (int i = 0; i < 8; i++) {
        v[i] = __expf(v[i] - bm);
        s += v[i];
    }
    #pragma unroll
    for (int o = 16; o > 0; o >>= 1)
        s += __shfl_xor_sync(0xffffffffu, s, o);
    if ((tid & 31) == 0) red[tid >> 5] = s;
    __syncthreads();
    float total = 0.0f;
    #pragma unroll
    for (int i = 0; i < 8; i++) total += red[i];

    float inv = 1.0f / total;
    #pragma unroll
    for (int i = 0; i < 8; i++)
        p[tid + i * 256] = v[i] * inv;
}

// ---------------------------------------------------------------------------
extern "C" void kernel_launch(void* const* d_in, const int* in_sizes, int n_in,
                              void* d_out, int out_size)
{
    const float* q = (const float*)d_in[0];   // [B, S, D]
    const float* k = (const float*)d_in[1];   // [B, D, S]
    const float* v = (const float*)d_in[2];   // [B, S, Dv]
    float* out = (float*)d_out;               // [B, S, Dv]

    float* scores;
    cudaGetSymbolAddress((void**)&scores, g_scores);

    const int B = ATT_B, S = ATT_S, D = ATT_D;

    cudaFuncSetAttribute(gemm_tf32,
                         cudaFuncAttributeMaxDynamicSharedMemorySize, SMEM_DYN);

    {   // scores = 0.1 * q @ k : M=S, N=S, K=D
        dim3 grid(S / 128, S / 128, B);
        gemm_tf32<<<grid, 128, SMEM_DYN>>>(q, k, scores,
                                           D, D, S, S, 0.1f,
                                           (long long)S * D, (long long)D * S,
                                           (long long)S * S);
    }
    {   // softmax rows
        softmax_rows<<<B * S, 256>>>(scores);
    }
    {   // out = scores @ v : M=S, N=D, K=S
        dim3 grid(D / 128, S / 128, B);
        gemm_tf32<<<grid, 128, SMEM_DYN>>>(scores, v, out,
                                           S, S, D, D, 1.0f,
                                           (long long)S * S, (long long)S * D,
                                           (long long)S * D);
    }
}

// round 6
// speedup vs baseline: 6.5162x; 2.3815x over previous
#include <cuda_runtime.h>
#include <math_constants.h>
#include <cstdint>

typedef unsigned int u32;
typedef unsigned long long u64;

// r = softmax( (q @ k) * 0.1 , -1) @ v ; B=8, S=2048, D=Dv=1024, fp32.
// Round 6: fix cp.async tail accounting (empty commit groups) + 6-stage
// pipeline with 4-deep loads (2-tile MMA slack on buffer reuse).

#if defined(__CUDA_ARCH_FEAT_SM103_ALL) || defined(__CUDA_ARCH_FEAT_SM100_ALL) || \
    defined(__CUDA_ARCH_SPECIFIC__)
#define HAS_TCGEN05 1
#else
#define HAS_TCGEN05 0
#endif

#define ATT_B 8
#define ATT_S 2048
#define ATT_D 1024

__device__ float g_scores[(size_t)ATT_B * ATT_S * ATT_S]; // 128 MB
__device__ float g_qr[(size_t)ATT_B * ATT_S * ATT_D];     // q rounded
__device__ float g_kT[(size_t)ATT_B * ATT_S * ATT_D];     // k^T rounded [S, D]
__device__ float g_vT[(size_t)ATT_B * ATT_D * ATT_S];     // v^T rounded [Dv, S]

// ---------------- PTX helpers ----------------
__device__ __forceinline__ u32 smem_u32(const void* p) {
    u32 a;
    asm("{ .reg .u64 t; cvta.to.shared.u64 t, %1; cvt.u32.u64 %0, t; }"
        : "=r"(a) : "l"(p));
    return a;
}
__device__ __forceinline__ u32 elect1() {
    u32 p;
    asm volatile("{ .reg .pred p; elect.sync _|p, 0xFFFFFFFF; selp.b32 %0,1,0,p; }"
                 : "=r"(p));
    return p;
}
__device__ __forceinline__ u32 cvt_tf32(float x) {
    u32 r;
    asm("cvt.rn.tf32.f32 %0, %1;" : "=r"(r) : "f"(x));
    return r;
}
__device__ __forceinline__ void mbar_init(u32 mbar, u32 cnt) {
    asm volatile("mbarrier.init.shared.b64 [%0], %1;" :: "r"(mbar), "r"(cnt) : "memory");
}
__device__ __forceinline__ void mbar_wait(u32 mbar, u32 parity) {
    asm volatile(
        "{ .reg .pred P;\n"
        "L%=: mbarrier.try_wait.parity.acquire.cta.shared::cta.b64 P, [%0], %1, 0x989680;\n"
        "@P bra D%=;\n"
        "bra L%=;\n"
        "D%=: }\n"
        :: "r"(mbar), "r"(parity) : "memory");
}
__device__ __forceinline__ void cp_async16(u32 dst, const void* src) {
    asm volatile("cp.async.cg.shared.global [%0], [%1], 16;"
                 :: "r"(dst), "l"(src) : "memory");
}
__device__ __forceinline__ void cp_commit() {
    asm volatile("cp.async.commit_group;" ::: "memory");
}
__device__ __forceinline__ void cp_wait3() {
    asm volatile("cp.async.wait_group 3;" ::: "memory");
}
__device__ __forceinline__ void fence_async_proxy() {
    asm volatile("fence.proxy.async.shared::cta;" ::: "memory");
}

#if HAS_TCGEN05
__device__ __forceinline__ void tmem_alloc(u32 smem_dst, u32 ncols) {
    asm volatile("tcgen05.alloc.cta_group::1.sync.aligned.shared::cta.b32 [%0], %1;"
                 :: "r"(smem_dst), "r"(ncols) : "memory");
}
__device__ __forceinline__ void tmem_relinquish() {
    asm volatile("tcgen05.relinquish_alloc_permit.cta_group::1.sync.aligned;");
}
__device__ __forceinline__ void tmem_dealloc(u32 tmem, u32 ncols) {
    asm volatile("tcgen05.dealloc.cta_group::1.sync.aligned.b32 %0, %1;"
                 :: "r"(tmem), "r"(ncols));
}
__device__ __forceinline__ void mma_tf32_ss(u32 d_tmem, u64 ad, u64 bd, u32 idesc, u32 en) {
    asm volatile(
        "{ .reg .pred p; setp.ne.u32 p, %4, 0;\n"
        "tcgen05.mma.cta_group::1.kind::tf32 [%0], %1, %2, %3, {%5,%5,%5,%5}, p;\n }"
        :: "r"(d_tmem), "l"(ad), "l"(bd), "r"(idesc), "r"(en), "r"(0u) : "memory");
}
__device__ __forceinline__ void mma_commit(u32 mbar) {
    asm volatile(
        "tcgen05.commit.cta_group::1.mbarrier::arrive::one.shared::cluster.b64 [%0];"
        :: "r"(mbar) : "memory");
}
__device__ __forceinline__ void tc_fence_after() {
    asm volatile("tcgen05.fence::after_thread_sync;" ::: "memory");
}
__device__ __forceinline__ void tmem_ld32(u32* r, u32 tmem) {
    asm volatile(
        "tcgen05.ld.sync.aligned.32x32b.x32.b32 "
        "{%0,%1,%2,%3,%4,%5,%6,%7,%8,%9,%10,%11,%12,%13,%14,%15,"
        "%16,%17,%18,%19,%20,%21,%22,%23,%24,%25,%26,%27,%28,%29,%30,%31}, [%32];"
        : "=r"(r[0]), "=r"(r[1]), "=r"(r[2]), "=r"(r[3]),
          "=r"(r[4]), "=r"(r[5]), "=r"(r[6]), "=r"(r[7]),
          "=r"(r[8]), "=r"(r[9]), "=r"(r[10]), "=r"(r[11]),
          "=r"(r[12]), "=r"(r[13]), "=r"(r[14]), "=r"(r[15]),
          "=r"(r[16]), "=r"(r[17]), "=r"(r[18]), "=r"(r[19]),
          "=r"(r[20]), "=r"(r[21]), "=r"(r[22]), "=r"(r[23]),
          "=r"(r[24]), "=r"(r[25]), "=r"(r[26]), "=r"(r[27]),
          "=r"(r[28]), "=r"(r[29]), "=r"(r[30]), "=r"(r[31])
        : "r"(tmem));
}
__device__ __forceinline__ void tmem_wait_ld() {
    asm volatile("tcgen05.wait::ld.sync.aligned;" ::: "memory");
}
#endif  // HAS_TCGEN05

#define SW128(o) ((o) ^ (((o) >> 3) & 0x70))

// SW128 K-major SMEM descriptor: layout=2, version=1, SBO=64, LBO=1
static constexpr u64 DESC_BASE =
    (2ull << 61) | (1ull << 46) | (64ull << 32) | (1ull << 16);
__device__ __forceinline__ u64 mk_desc(u32 addr) {
    return DESC_BASE | ((u64)(addr >> 4) & 0x3FFF);
}

// idesc kind::tf32: dtype=F32, atype=btype=TF32, N=128, M=128
static constexpr u32 IDESC_TF32 =
    (1u << 4) | (2u << 7) | (2u << 10) | ((128u / 8) << 17) | ((128u / 16) << 24);

#define TK 32                  // fp32 per SW128 row
#define TILE_BYTES 16384       // 128 rows * 128 B
#define STAGES 6               // smem slots
#define PRELOAD 4              // load pipeline depth (wait_group 3)
#define SMEM_CTRL 2048
#define SMEM_DYN (SMEM_CTRL + STAGES * 2 * TILE_BYTES)   // ~198.7 KB

// ---------------------------------------------------------------------------
// tcgen05 tf32 batched GEMM:  C[M,N] = alpha * A[M,K] @ BT[N,K]^T
// Operands must already be tf32-rounded. A row-major, BT row-major (N rows).
// ---------------------------------------------------------------------------
__global__ __launch_bounds__(128) void gemm_tf32_pipe(
    const float* __restrict__ A, const float* __restrict__ BT,
    float* __restrict__ C, int K, int lda, int ldbt, int ldc, float alpha,
    long long strideA, long long strideB, long long strideC)
{
#if HAS_TCGEN05
    extern __shared__ char smem[];
    const u32 smem_base = smem_u32(smem);
    const u32 tiles_addr = (smem_base + 1024 + 1023) & ~1023u;

    const int tid = threadIdx.x;
    const int wid = tid >> 5;
    const int lid = tid & 31;

    const int b = blockIdx.z;
    A  += (long long)b * strideA;
    BT += (long long)b * strideB;
    C  += (long long)b * strideC;

    const int row0 = blockIdx.y * 128;
    const int col0 = blockIdx.x * 128;

    const u32 mbar0 = smem_base + 8;       // STAGES slot barriers
    const u32 mbarF = smem_base + 8 + 8 * STAGES;

    if (tid == 0) {
        #pragma unroll
        for (int s = 0; s < STAGES; s++) mbar_init(mbar0 + 8 * s, 1);
        mbar_init(mbarF, 1);
    }
    if (wid == 0) {
        tmem_alloc(smem_base + 0, 128);
        tmem_relinquish();
    }
    __syncthreads();
    u32 tmem;
    asm volatile("ld.shared.b32 %0, [%1];" : "=r"(tmem) : "r"(smem_base + 0));

    // per-thread load mapping: 16B chunk c16 within 128B row, 8 rows strided 16
    const int c16   = tid & 7;
    const int rbase = tid >> 3;

    const float* Abase = A  + (long long)(row0 + rbase) * lda  + c16 * 4;
    const float* Bbase = BT + (long long)(col0 + rbase) * ldbt + c16 * 4;

    const int KT = K / TK;
    u32 phases = 0;

    auto load_tile = [&](int kt) {
        const int slot = kt % STAGES;
        const u32 At = tiles_addr + slot * 2 * TILE_BYTES;
        const u32 Bt = At + TILE_BYTES;
        const float* as = Abase + kt * TK;
        const float* bs = Bbase + kt * TK;
        #pragma unroll
        for (int p = 0; p < 8; p++) {
            const int r = rbase + p * 16;
            const u32 off = SW128((u32)(r * 128 + c16 * 16));
            cp_async16(At + off, as + (long long)(p * 16) * lda);
            cp_async16(Bt + off, bs + (long long)(p * 16) * ldbt);
        }
        cp_commit();
    };

    // prologue: 4 tiles in flight
    #pragma unroll
    for (int t = 0; t < PRELOAD; t++) load_tile(t);

    for (int i = 0; i < KT; i++) {
        // commits so far = PRELOAD + i (one per past iteration, real or empty)
        // pending <= 3  =>  tile i complete (this thread)
        cp_wait3();
        fence_async_proxy();
        __syncthreads();          // all threads' tile-i chunks visible

        if (wid == 0 && elect1()) {
            const int slot = i % STAGES;
            const u32 At = tiles_addr + slot * 2 * TILE_BYTES;
            const u64 ad = mk_desc(At);
            const u64 bd = mk_desc(At + TILE_BYTES);
            #pragma unroll
            for (int sub = 0; sub < 4; sub++)
                mma_tf32_ss(tmem, ad + sub * 2, bd + sub * 2, IDESC_TF32,
                            (i | sub) != 0);
            mma_commit(mbar0 + 8 * slot);
        }

        const int j = i + PRELOAD;
        if (j < KT) {
            // slot j%STAGES previously held tile j-STAGES = i-2:
            // wait for its MMA before overwriting (2 tiles of slack).
            if (i >= 2) {
                const int s = (i - 2) % STAGES;
                mbar_wait(mbar0 + 8 * s, (phases >> s) & 1);
                phases ^= (1u << s);
            }
            load_tile(j);
        } else {
            cp_commit();          // empty group: keeps wait_group accounting exact
        }
    }

    // final drain: commit after all MMAs, single-use barrier
    if (wid == 0 && elect1()) mma_commit(mbarF);
    mbar_wait(mbarF, 0);
    tc_fence_after();

    // epilogue: warp w -> rows w*32..w*32+31
    const int grow = row0 + wid * 32 + lid;
    float* crow = C + (long long)grow * ldc + col0;
    #pragma unroll
    for (int cb = 0; cb < 4; cb++) {
        u32 r[32];
        tmem_ld32(r, tmem + cb * 32);
        tmem_wait_ld();
        #pragma unroll
        for (int jj = 0; jj < 32; jj += 4) {
            float4 t;
            t.x = alpha * __uint_as_float(r[jj + 0]);
            t.y = alpha * __uint_as_float(r[jj + 1]);
            t.z = alpha * __uint_as_float(r[jj + 2]);
            t.w = alpha * __uint_as_float(r[jj + 3]);
            *(float4*)(crow + cb * 32 + jj) = t;
        }
    }

    __syncthreads();
    if (wid == 0) tmem_dealloc(tmem, 128);
#endif  // HAS_TCGEN05
}

// ---------------------------------------------------------------------------
// Pre-pass: elementwise tf32 rounding (q)
// ---------------------------------------------------------------------------
__global__ __launch_bounds__(256) void round_tf32_vec(
    const float* __restrict__ src, float* __restrict__ dst)
{
    const long long i = ((long long)blockIdx.x * 256 + threadIdx.x) * 4;
    float4 t = *(const float4*)(src + i);
    uint4 u;
    u.x = cvt_tf32(t.x); u.y = cvt_tf32(t.y);
    u.z = cvt_tf32(t.z); u.w = cvt_tf32(t.w);
    *(uint4*)(dst + i) = u;
}

// ---------------------------------------------------------------------------
// Pre-pass: batched transpose + tf32 round: src [R, C] -> dst [C, R]
// ---------------------------------------------------------------------------
__global__ __launch_bounds__(256) void transpose_round(
    const float* __restrict__ src, float* __restrict__ dst, int R, int C)
{
    __shared__ float t[32][33];
    const long long boff = (long long)blockIdx.z * R * C;
    src += boff; dst += boff;
    const int r0 = blockIdx.y * 32, c0 = blockIdx.x * 32;
    const int tx = threadIdx.x, ty = threadIdx.y;   // (32, 8)
    #pragma unroll
    for (int i = 0; i < 4; i++)
        t[ty + 8 * i][tx] = src[(long long)(r0 + ty + 8 * i) * C + c0 + tx];
    __syncthreads();
    #pragma unroll
    for (int i = 0; i < 4; i++)
        dst[(long long)(c0 + ty + 8 * i) * R + r0 + tx] =
            __uint_as_float(cvt_tf32(t[tx][ty + 8 * i]));
}

// ---------------------------------------------------------------------------
// Row softmax, in place (rows of 2048), output tf32-rounded.
// ---------------------------------------------------------------------------
__global__ __launch_bounds__(256) void softmax_rows(float* __restrict__ scores)
{
    const long long row = blockIdx.x;
    float* p = scores + row * (long long)ATT_S;
    const int tid = threadIdx.x;

    float v[8];
    float m = -CUDART_INF_F;
    #pragma unroll
    for (int i = 0; i < 8; i++) {
        v[i] = p[tid + i * 256];
        m = fmaxf(m, v[i]);
    }
    __shared__ float red[8];
    #pragma unroll
    for (int o = 16; o > 0; o >>= 1)
        m = fmaxf(m, __shfl_xor_sync(0xffffffffu, m, o));
    if ((tid & 31) == 0) red[tid >> 5] = m;
    __syncthreads();
    float bm = red[0];
    #pragma unroll
    for (int i = 1; i < 8; i++) bm = fmaxf(bm, red[i]);
    __syncthreads();

    float s = 0.0f;
    #pragma unroll
    for (int i = 0; i < 8; i++) {
        v[i] = __expf(v[i] - bm);
        s += v[i];
    }
    #pragma unroll
    for (int o = 16; o > 0; o >>= 1)
        s += __shfl_xor_sync(0xffffffffu, s, o);
    if ((tid & 31) == 0) red[tid >> 5] = s;
    __syncthreads();
    float total = 0.0f;
    #pragma unroll
    for (int i = 0; i < 8; i++) total += red[i];

    float inv = 1.0f / total;
    #pragma unroll
    for (int i = 0; i < 8; i++)
        p[tid + i * 256] = __uint_as_float(cvt_tf32(v[i] * inv));
}

// ---------------------------------------------------------------------------
extern "C" void kernel_launch(void* const* d_in, const int* in_sizes, int n_in,
                              void* d_out, int out_size)
{
    const float* q = (const float*)d_in[0];   // [B, S, D]
    const float* k = (const float*)d_in[1];   // [B, D, S]
    const float* v = (const float*)d_in[2];   // [B, S, Dv]
    float* out = (float*)d_out;               // [B, S, Dv]

    float *scores, *qr, *kT, *vT;
    cudaGetSymbolAddress((void**)&scores, g_scores);
    cudaGetSymbolAddress((void**)&qr, g_qr);
    cudaGetSymbolAddress((void**)&kT, g_kT);
    cudaGetSymbolAddress((void**)&vT, g_vT);

    const int B = ATT_B, S = ATT_S, D = ATT_D;

    cudaFuncSetAttribute(gemm_tf32_pipe,
                         cudaFuncAttributeMaxDynamicSharedMemorySize, SMEM_DYN);

    // pre-pass: round q; transpose+round k (DxS -> SxD) and v (SxD -> DxS)
    {
        long long nq = (long long)B * S * D;
        round_tf32_vec<<<(unsigned)(nq / (256 * 4)), 256>>>(q, qr);
        dim3 blk(32, 8);
        transpose_round<<<dim3(S / 32, D / 32, B), blk>>>(k, kT, D, S);
        transpose_round<<<dim3(D / 32, S / 32, B), blk>>>(v, vT, S, D);
    }

    {   // scores = 0.1 * qr @ kT^T : M=S, N=S, K=D
        dim3 grid(S / 128, S / 128, B);
        gemm_tf32_pipe<<<grid, 128, SMEM_DYN>>>(qr, kT, scores,
                                                D, D, D, S, 0.1f,
                                                (long long)S * D, (long long)S * D,
                                                (long long)S * S);
    }
    {   // softmax rows (tf32-rounded output)
        softmax_rows<<<B * S, 256>>>(scores);
    }
    {   // out = scores @ vT^T : M=S, N=D, K=S
        dim3 grid(D / 128, S / 128, B);
        gemm_tf32_pipe<<<grid, 128, SMEM_DYN>>>(scores, vT, out,
                                                S, S, S, D, 1.0f,
                                                (long long)S * S, (long long)D * S,
                                                (long long)S * D);
    }
}

// round 7
// speedup vs baseline: 10.9507x; 1.6805x over previous
#include <cuda_runtime.h>
#include <math_constants.h>
#include <cstdint>

typedef unsigned int u32;
typedef unsigned long long u64;

// r = softmax( (q @ k) * 0.1 , -1) @ v ; B=8, S=2048, D=Dv=1024, fp32.
// Round 7: 128x256 output tile (2x N=128 MMAs into TMEM cols 0/128) to cut
// L2 tile traffic 25% and halve CTA count. 4-stage cp.async pipeline.

#if defined(__CUDA_ARCH_FEAT_SM103_ALL) || defined(__CUDA_ARCH_FEAT_SM100_ALL) || \
    defined(__CUDA_ARCH_SPECIFIC__)
#define HAS_TCGEN05 1
#else
#define HAS_TCGEN05 0
#endif

#define ATT_B 8
#define ATT_S 2048
#define ATT_D 1024

__device__ float g_scores[(size_t)ATT_B * ATT_S * ATT_S];
__device__ float g_qr[(size_t)ATT_B * ATT_S * ATT_D];
__device__ float g_kT[(size_t)ATT_B * ATT_S * ATT_D];
__device__ float g_vT[(size_t)ATT_B * ATT_D * ATT_S];

// ---------------- PTX helpers ----------------
__device__ __forceinline__ u32 smem_u32(const void* p) {
    u32 a;
    asm("{ .reg .u64 t; cvta.to.shared.u64 t, %1; cvt.u32.u64 %0, t; }"
        : "=r"(a) : "l"(p));
    return a;
}
__device__ __forceinline__ u32 elect1() {
    u32 p;
    asm volatile("{ .reg .pred p; elect.sync _|p, 0xFFFFFFFF; selp.b32 %0,1,0,p; }"
                 : "=r"(p));
    return p;
}
__device__ __forceinline__ u32 cvt_tf32(float x) {
    u32 r;
    asm("cvt.rn.tf32.f32 %0, %1;" : "=r"(r) : "f"(x));
    return r;
}
__device__ __forceinline__ void mbar_init(u32 mbar, u32 cnt) {
    asm volatile("mbarrier.init.shared.b64 [%0], %1;" :: "r"(mbar), "r"(cnt) : "memory");
}
__device__ __forceinline__ void mbar_wait(u32 mbar, u32 parity) {
    asm volatile(
        "{ .reg .pred P;\n"
        "L%=: mbarrier.try_wait.parity.acquire.cta.shared::cta.b64 P, [%0], %1, 0x989680;\n"
        "@P bra D%=;\n"
        "bra L%=;\n"
        "D%=: }\n"
        :: "r"(mbar), "r"(parity) : "memory");
}
__device__ __forceinline__ void cp_async16(u32 dst, const void* src) {
    asm volatile("cp.async.cg.shared.global [%0], [%1], 16;"
                 :: "r"(dst), "l"(src) : "memory");
}
__device__ __forceinline__ void cp_commit() {
    asm volatile("cp.async.commit_group;" ::: "memory");
}
__device__ __forceinline__ void cp_wait2() {
    asm volatile("cp.async.wait_group 2;" ::: "memory");
}
__device__ __forceinline__ void fence_async_proxy() {
    asm volatile("fence.proxy.async.shared::cta;" ::: "memory");
}

#if HAS_TCGEN05
__device__ __forceinline__ void tmem_alloc(u32 smem_dst, u32 ncols) {
    asm volatile("tcgen05.alloc.cta_group::1.sync.aligned.shared::cta.b32 [%0], %1;"
                 :: "r"(smem_dst), "r"(ncols) : "memory");
}
__device__ __forceinline__ void tmem_relinquish() {
    asm volatile("tcgen05.relinquish_alloc_permit.cta_group::1.sync.aligned;");
}
__device__ __forceinline__ void tmem_dealloc(u32 tmem, u32 ncols) {
    asm volatile("tcgen05.dealloc.cta_group::1.sync.aligned.b32 %0, %1;"
                 :: "r"(tmem), "r"(ncols));
}
__device__ __forceinline__ void mma_tf32_ss(u32 d_tmem, u64 ad, u64 bd, u32 idesc, u32 en) {
    asm volatile(
        "{ .reg .pred p; setp.ne.u32 p, %4, 0;\n"
        "tcgen05.mma.cta_group::1.kind::tf32 [%0], %1, %2, %3, {%5,%5,%5,%5}, p;\n }"
        :: "r"(d_tmem), "l"(ad), "l"(bd), "r"(idesc), "r"(en), "r"(0u) : "memory");
}
__device__ __forceinline__ void mma_commit(u32 mbar) {
    asm volatile(
        "tcgen05.commit.cta_group::1.mbarrier::arrive::one.shared::cluster.b64 [%0];"
        :: "r"(mbar) : "memory");
}
__device__ __forceinline__ void tc_fence_after() {
    asm volatile("tcgen05.fence::after_thread_sync;" ::: "memory");
}
__device__ __forceinline__ void tmem_ld32(u32* r, u32 tmem) {
    asm volatile(
        "tcgen05.ld.sync.aligned.32x32b.x32.b32 "
        "{%0,%1,%2,%3,%4,%5,%6,%7,%8,%9,%10,%11,%12,%13,%14,%15,"
        "%16,%17,%18,%19,%20,%21,%22,%23,%24,%25,%26,%27,%28,%29,%30,%31}, [%32];"
        : "=r"(r[0]), "=r"(r[1]), "=r"(r[2]), "=r"(r[3]),
          "=r"(r[4]), "=r"(r[5]), "=r"(r[6]), "=r"(r[7]),
          "=r"(r[8]), "=r"(r[9]), "=r"(r[10]), "=r"(r[11]),
          "=r"(r[12]), "=r"(r[13]), "=r"(r[14]), "=r"(r[15]),
          "=r"(r[16]), "=r"(r[17]), "=r"(r[18]), "=r"(r[19]),
          "=r"(r[20]), "=r"(r[21]), "=r"(r[22]), "=r"(r[23]),
          "=r"(r[24]), "=r"(r[25]), "=r"(r[26]), "=r"(r[27]),
          "=r"(r[28]), "=r"(r[29]), "=r"(r[30]), "=r"(r[31])
        : "r"(tmem));
}
__device__ __forceinline__ void tmem_wait_ld() {
    asm volatile("tcgen05.wait::ld.sync.aligned;" ::: "memory");
}
#endif  // HAS_TCGEN05

#define SW128(o) ((o) ^ (((o) >> 3) & 0x70))

static constexpr u64 DESC_BASE =
    (2ull << 61) | (1ull << 46) | (64ull << 32) | (1ull << 16);
__device__ __forceinline__ u64 mk_desc(u32 addr) {
    return DESC_BASE | ((u64)(addr >> 4) & 0x3FFF);
}

// idesc kind::tf32: dtype=F32, atype=btype=TF32, N=128, M=128
static constexpr u32 IDESC_TF32 =
    (1u << 4) | (2u << 7) | (2u << 10) | ((128u / 8) << 17) | ((128u / 16) << 24);

#define TK 32                   // fp32 per SW128 row
#define TN_TILE 256             // output tile width
#define A_BYTES 16384           // 128 x 128B
#define B_BYTES 32768           // 256 x 128B
#define STAGE_BYTES (A_BYTES + B_BYTES)
#define STAGES 4
#define PRELOAD 3
#define SMEM_CTRL 2048
#define SMEM_DYN (SMEM_CTRL + STAGES * STAGE_BYTES)   // 198,656 B

// ---------------------------------------------------------------------------
// tcgen05 tf32 batched GEMM:  C[M,N] = alpha * A[M,K] @ BT[N,K]^T
// 128 x 256 tile per CTA. Operands pre-rounded to tf32.
// ---------------------------------------------------------------------------
__global__ __launch_bounds__(128) void gemm_tf32_pipe(
    const float* __restrict__ A, const float* __restrict__ BT,
    float* __restrict__ C, int K, int lda, int ldbt, int ldc, float alpha,
    long long strideA, long long strideB, long long strideC)
{
#if HAS_TCGEN05
    extern __shared__ char smem[];
    const u32 smem_base = smem_u32(smem);
    const u32 tiles_addr = (smem_base + 1024 + 1023) & ~1023u;

    const int tid = threadIdx.x;
    const int wid = tid >> 5;
    const int lid = tid & 31;

    const int b = blockIdx.z;
    A  += (long long)b * strideA;
    BT += (long long)b * strideB;
    C  += (long long)b * strideC;

    const int row0 = blockIdx.y * 128;
    const int col0 = blockIdx.x * TN_TILE;

    const u32 mbar0 = smem_base + 8;       // STAGES slot barriers
    const u32 mbarF = smem_base + 8 + 8 * STAGES;

    if (tid == 0) {
        #pragma unroll
        for (int s = 0; s < STAGES; s++) mbar_init(mbar0 + 8 * s, 1);
        mbar_init(mbarF, 1);
    }
    if (wid == 0) {
        tmem_alloc(smem_base + 0, 256);
        tmem_relinquish();
    }
    __syncthreads();
    u32 tmem;
    asm volatile("ld.shared.b32 %0, [%1];" : "=r"(tmem) : "r"(smem_base + 0));

    const int c16   = tid & 7;      // 16B chunk within 128B row
    const int rbase = tid >> 3;     // 0..15

    const float* Abase = A  + (long long)(row0 + rbase) * lda  + c16 * 4;
    const float* Bbase = BT + (long long)(col0 + rbase) * ldbt + c16 * 4;

    const int KT = K / TK;
    u32 phases = 0;

    auto load_tile = [&](int kt) {
        const int slot = kt % STAGES;
        const u32 At = tiles_addr + slot * STAGE_BYTES;
        const u32 Bt = At + A_BYTES;
        const float* as = Abase + kt * TK;
        const float* bs = Bbase + kt * TK;
        #pragma unroll
        for (int p = 0; p < 8; p++) {       // A: rows 0..127
            const int r = rbase + p * 16;
            cp_async16(At + SW128((u32)(r * 128 + c16 * 16)),
                       as + (long long)(p * 16) * lda);
        }
        #pragma unroll
        for (int p = 0; p < 16; p++) {      // B: rows 0..255
            const int r = rbase + p * 16;
            cp_async16(Bt + SW128((u32)(r * 128 + c16 * 16)),
                       bs + (long long)(p * 16) * ldbt);
        }
        cp_commit();
    };

    #pragma unroll
    for (int t = 0; t < PRELOAD; t++) load_tile(t);

    for (int i = 0; i < KT; i++) {
        // commits so far = PRELOAD + i ; pending <= 2 => tile i landed
        cp_wait2();
        fence_async_proxy();
        __syncthreads();

        if (wid == 0 && elect1()) {
            const int slot = i % STAGES;
            const u32 At = tiles_addr + slot * STAGE_BYTES;
            const u64 ad  = mk_desc(At);
            const u64 bd0 = mk_desc(At + A_BYTES);            // B rows 0..127
            const u64 bd1 = mk_desc(At + A_BYTES + 16384);    // B rows 128..255
            #pragma unroll
            for (int sub = 0; sub < 4; sub++) {
                const u32 en = (i | sub) != 0;
                mma_tf32_ss(tmem,       ad + sub * 2, bd0 + sub * 2, IDESC_TF32, en);
                mma_tf32_ss(tmem + 128, ad + sub * 2, bd1 + sub * 2, IDESC_TF32, en);
            }
            mma_commit(mbar0 + 8 * slot);
        }

        const int j = i + PRELOAD;
        if (j < KT) {
            // slot j%STAGES previously held tile j-STAGES = i-1
            if (i >= 1) {
                const int s = (i - 1) % STAGES;
                mbar_wait(mbar0 + 8 * s, (phases >> s) & 1);
                phases ^= (1u << s);
            }
            load_tile(j);
        } else {
            cp_commit();   // empty group keeps wait_group accounting exact
        }
    }

    if (wid == 0 && elect1()) mma_commit(mbarF);
    mbar_wait(mbarF, 0);
    tc_fence_after();

    // epilogue: warp w -> rows w*32..w*32+31 ; 8 col-chunks of 32
    const int grow = row0 + wid * 32 + lid;
    float* crow = C + (long long)grow * ldc + col0;
    #pragma unroll
    for (int cb = 0; cb < 8; cb++) {
        u32 r[32];
        tmem_ld32(r, tmem + cb * 32);
        tmem_wait_ld();
        #pragma unroll
        for (int jj = 0; jj < 32; jj += 4) {
            float4 t;
            t.x = alpha * __uint_as_float(r[jj + 0]);
            t.y = alpha * __uint_as_float(r[jj + 1]);
            t.z = alpha * __uint_as_float(r[jj + 2]);
            t.w = alpha * __uint_as_float(r[jj + 3]);
            *(float4*)(crow + cb * 32 + jj) = t;
        }
    }

    __syncthreads();
    if (wid == 0) tmem_dealloc(tmem, 256);
#endif  // HAS_TCGEN05
}

// ---------------------------------------------------------------------------
__global__ __launch_bounds__(256) void round_tf32_vec(
    const float* __restrict__ src, float* __restrict__ dst)
{
    const long long i = ((long long)blockIdx.x * 256 + threadIdx.x) * 4;
    float4 t = *(const float4*)(src + i);
    uint4 u;
    u.x = cvt_tf32(t.x); u.y = cvt_tf32(t.y);
    u.z = cvt_tf32(t.z); u.w = cvt_tf32(t.w);
    *(uint4*)(dst + i) = u;
}

__global__ __launch_bounds__(256) void transpose_round(
    const float* __restrict__ src, float* __restrict__ dst, int R, int C)
{
    __shared__ float t[32][33];
    const long long boff = (long long)blockIdx.z * R * C;
    src += boff; dst += boff;
    const int r0 = blockIdx.y * 32, c0 = blockIdx.x * 32;
    const int tx = threadIdx.x, ty = threadIdx.y;   // (32, 8)
    #pragma unroll
    for (int i = 0; i < 4; i++)
        t[ty + 8 * i][tx] = src[(long long)(r0 + ty + 8 * i) * C + c0 + tx];
    __syncthreads();
    #pragma unroll
    for (int i = 0; i < 4; i++)
        dst[(long long)(c0 + ty + 8 * i) * R + r0 + tx] =
            __uint_as_float(cvt_tf32(t[tx][ty + 8 * i]));
}

__global__ __launch_bounds__(256) void softmax_rows(float* __restrict__ scores)
{
    const long long row = blockIdx.x;
    float* p = scores + row * (long long)ATT_S;
    const int tid = threadIdx.x;

    float v[8];
    float m = -CUDART_INF_F;
    #pragma unroll
    for (int i = 0; i < 8; i++) {
        v[i] = p[tid + i * 256];
        m = fmaxf(m, v[i]);
    }
    __shared__ float red[8];
    #pragma unroll
    for (int o = 16; o > 0; o >>= 1)
        m = fmaxf(m, __shfl_xor_sync(0xffffffffu, m, o));
    if ((tid & 31) == 0) red[tid >> 5] = m;
    __syncthreads();
    float bm = red[0];
    #pragma unroll
    for (int i = 1; i < 8; i++) bm = fmaxf(bm, red[i]);
    __syncthreads();

    float s = 0.0f;
    #pragma unroll
    for (int i = 0; i < 8; i++) {
        v[i] = __expf(v[i] - bm);
        s += v[i];
    }
    #pragma unroll
    for (int o = 16; o > 0; o >>= 1)
        s += __shfl_xor_sync(0xffffffffu, s, o);
    if ((tid & 31) == 0) red[tid >> 5] = s;
    __syncthreads();
    float total = 0.0f;
    #pragma unroll
    for (int i = 0; i < 8; i++) total += red[i];

    float inv = 1.0f / total;
    #pragma unroll
    for (int i = 0; i < 8; i++)
        p[tid + i * 256] = __uint_as_float(cvt_tf32(v[i] * inv));
}

// ---------------------------------------------------------------------------
extern "C" void kernel_launch(void* const* d_in, const int* in_sizes, int n_in,
                              void* d_out, int out_size)
{
    const float* q = (const float*)d_in[0];   // [B, S, D]
    const float* k = (const float*)d_in[1];   // [B, D, S]
    const float* v = (const float*)d_in[2];   // [B, S, Dv]
    float* out = (float*)d_out;               // [B, S, Dv]

    float *scores, *qr, *kT, *vT;
    cudaGetSymbolAddress((void**)&scores, g_scores);
    cudaGetSymbolAddress((void**)&qr, g_qr);
    cudaGetSymbolAddress((void**)&kT, g_kT);
    cudaGetSymbolAddress((void**)&vT, g_vT);

    const int B = ATT_B, S = ATT_S, D = ATT_D;

    cudaFuncSetAttribute(gemm_tf32_pipe,
                         cudaFuncAttributeMaxDynamicSharedMemorySize, SMEM_DYN);

    {
        long long nq = (long long)B * S * D;
        round_tf32_vec<<<(unsigned)(nq / (256 * 4)), 256>>>(q, qr);
        dim3 blk(32, 8);
        transpose_round<<<dim3(S / 32, D / 32, B), blk>>>(k, kT, D, S);
        transpose_round<<<dim3(D / 32, S / 32, B), blk>>>(v, vT, S, D);
    }

    {   // scores = 0.1 * qr @ kT^T : M=S, N=S, K=D
        dim3 grid(S / TN_TILE, S / 128, B);
        gemm_tf32_pipe<<<grid, 128, SMEM_DYN>>>(qr, kT, scores,
                                                D, D, D, S, 0.1f,
                                                (long long)S * D, (long long)S * D,
                                                (long long)S * S);
    }
    {
        softmax_rows<<<B * S, 256>>>(scores);
    }
    {   // out = scores @ vT^T : M=S, N=D, K=S
        dim3 grid(D / TN_TILE, S / 128, B);
        gemm_tf32_pipe<<<grid, 128, SMEM_DYN>>>(scores, vT, out,
                                                S, S, S, D, 1.0f,
                                                (long long)S * S, (long long)D * S,
                                                (long long)S * D);
    }
}

// round 8
// speedup vs baseline: 11.8303x; 1.0803x over previous
#include <cuda_runtime.h>
#include <math_constants.h>
#include <cstdint>

typedef unsigned int u32;
typedef unsigned long long u64;

// r = softmax( (q @ k) * 0.1 , -1) @ v ; B=8, S=2048, D=Dv=1024, fp32.
// Round 8: 256x256 output tile. Two M=128 row-block MMAs share one B tile
// (TMEM cols 0-255 / 256-511). 64KB stages x3, cp.async pipeline depth 2.

#if defined(__CUDA_ARCH_FEAT_SM103_ALL) || defined(__CUDA_ARCH_FEAT_SM100_ALL) || \
    defined(__CUDA_ARCH_SPECIFIC__)
#define HAS_TCGEN05 1
#else
#define HAS_TCGEN05 0
#endif

#define ATT_B 8
#define ATT_S 2048
#define ATT_D 1024

__device__ float g_scores[(size_t)ATT_B * ATT_S * ATT_S];
__device__ float g_qr[(size_t)ATT_B * ATT_S * ATT_D];
__device__ float g_kT[(size_t)ATT_B * ATT_S * ATT_D];
__device__ float g_vT[(size_t)ATT_B * ATT_D * ATT_S];

// ---------------- PTX helpers ----------------
__device__ __forceinline__ u32 smem_u32(const void* p) {
    u32 a;
    asm("{ .reg .u64 t; cvta.to.shared.u64 t, %1; cvt.u32.u64 %0, t; }"
        : "=r"(a) : "l"(p));
    return a;
}
__device__ __forceinline__ u32 elect1() {
    u32 p;
    asm volatile("{ .reg .pred p; elect.sync _|p, 0xFFFFFFFF; selp.b32 %0,1,0,p; }"
                 : "=r"(p));
    return p;
}
__device__ __forceinline__ u32 cvt_tf32(float x) {
    u32 r;
    asm("cvt.rn.tf32.f32 %0, %1;" : "=r"(r) : "f"(x));
    return r;
}
__device__ __forceinline__ void mbar_init(u32 mbar, u32 cnt) {
    asm volatile("mbarrier.init.shared.b64 [%0], %1;" :: "r"(mbar), "r"(cnt) : "memory");
}
__device__ __forceinline__ void mbar_wait(u32 mbar, u32 parity) {
    asm volatile(
        "{ .reg .pred P;\n"
        "L%=: mbarrier.try_wait.parity.acquire.cta.shared::cta.b64 P, [%0], %1, 0x989680;\n"
        "@P bra D%=;\n"
        "bra L%=;\n"
        "D%=: }\n"
        :: "r"(mbar), "r"(parity) : "memory");
}
__device__ __forceinline__ void cp_async16(u32 dst, const void* src) {
    asm volatile("cp.async.cg.shared.global [%0], [%1], 16;"
                 :: "r"(dst), "l"(src) : "memory");
}
__device__ __forceinline__ void cp_commit() {
    asm volatile("cp.async.commit_group;" ::: "memory");
}
__device__ __forceinline__ void cp_wait1() {
    asm volatile("cp.async.wait_group 1;" ::: "memory");
}
__device__ __forceinline__ void fence_async_proxy() {
    asm volatile("fence.proxy.async.shared::cta;" ::: "memory");
}

#if HAS_TCGEN05
__device__ __forceinline__ void tmem_alloc(u32 smem_dst, u32 ncols) {
    asm volatile("tcgen05.alloc.cta_group::1.sync.aligned.shared::cta.b32 [%0], %1;"
                 :: "r"(smem_dst), "r"(ncols) : "memory");
}
__device__ __forceinline__ void tmem_relinquish() {
    asm volatile("tcgen05.relinquish_alloc_permit.cta_group::1.sync.aligned;");
}
__device__ __forceinline__ void tmem_dealloc(u32 tmem, u32 ncols) {
    asm volatile("tcgen05.dealloc.cta_group::1.sync.aligned.b32 %0, %1;"
                 :: "r"(tmem), "r"(ncols));
}
__device__ __forceinline__ void mma_tf32_ss(u32 d_tmem, u64 ad, u64 bd, u32 idesc, u32 en) {
    asm volatile(
        "{ .reg .pred p; setp.ne.u32 p, %4, 0;\n"
        "tcgen05.mma.cta_group::1.kind::tf32 [%0], %1, %2, %3, {%5,%5,%5,%5}, p;\n }"
        :: "r"(d_tmem), "l"(ad), "l"(bd), "r"(idesc), "r"(en), "r"(0u) : "memory");
}
__device__ __forceinline__ void mma_commit(u32 mbar) {
    asm volatile(
        "tcgen05.commit.cta_group::1.mbarrier::arrive::one.shared::cluster.b64 [%0];"
        :: "r"(mbar) : "memory");
}
__device__ __forceinline__ void tc_fence_after() {
    asm volatile("tcgen05.fence::after_thread_sync;" ::: "memory");
}
__device__ __forceinline__ void tmem_ld32(u32* r, u32 tmem) {
    asm volatile(
        "tcgen05.ld.sync.aligned.32x32b.x32.b32 "
        "{%0,%1,%2,%3,%4,%5,%6,%7,%8,%9,%10,%11,%12,%13,%14,%15,"
        "%16,%17,%18,%19,%20,%21,%22,%23,%24,%25,%26,%27,%28,%29,%30,%31}, [%32];"
        : "=r"(r[0]), "=r"(r[1]), "=r"(r[2]), "=r"(r[3]),
          "=r"(r[4]), "=r"(r[5]), "=r"(r[6]), "=r"(r[7]),
          "=r"(r[8]), "=r"(r[9]), "=r"(r[10]), "=r"(r[11]),
          "=r"(r[12]), "=r"(r[13]), "=r"(r[14]), "=r"(r[15]),
          "=r"(r[16]), "=r"(r[17]), "=r"(r[18]), "=r"(r[19]),
          "=r"(r[20]), "=r"(r[21]), "=r"(r[22]), "=r"(r[23]),
          "=r"(r[24]), "=r"(r[25]), "=r"(r[26]), "=r"(r[27]),
          "=r"(r[28]), "=r"(r[29]), "=r"(r[30]), "=r"(r[31])
        : "r"(tmem));
}
__device__ __forceinline__ void tmem_wait_ld() {
    asm volatile("tcgen05.wait::ld.sync.aligned;" ::: "memory");
}
#endif  // HAS_TCGEN05

#define SW128(o) ((o) ^ (((o) >> 3) & 0x70))

static constexpr u64 DESC_BASE =
    (2ull << 61) | (1ull << 46) | (64ull << 32) | (1ull << 16);
__device__ __forceinline__ u64 mk_desc(u32 addr) {
    return DESC_BASE | ((u64)(addr >> 4) & 0x3FFF);
}

// idesc kind::tf32: dtype=F32, atype=btype=TF32, N=128, M=128
static constexpr u32 IDESC_TF32 =
    (1u << 4) | (2u << 7) | (2u << 10) | ((128u / 8) << 17) | ((128u / 16) << 24);

#define TK 32                   // fp32 per SW128 row
#define TM_TILE 256             // output tile height (2 x M=128 MMA blocks)
#define TN_TILE 256             // output tile width  (2 x N=128 MMA halves)
#define A_BYTES 32768           // 256 rows x 128B
#define B_BYTES 32768           // 256 rows x 128B
#define STAGE_BYTES (A_BYTES + B_BYTES)   // 64KB
#define STAGES 3
#define PRELOAD 2
#define SMEM_CTRL 2048
#define SMEM_DYN (SMEM_CTRL + STAGES * STAGE_BYTES)   // 198,656 B

// ---------------------------------------------------------------------------
// tcgen05 tf32 batched GEMM:  C[M,N] = alpha * A[M,K] @ BT[N,K]^T
// 256 x 256 tile per CTA; B tile shared by both row-block MMAs.
// ---------------------------------------------------------------------------
__global__ __launch_bounds__(128) void gemm_tf32_pipe(
    const float* __restrict__ A, const float* __restrict__ BT,
    float* __restrict__ C, int K, int lda, int ldbt, int ldc, float alpha,
    long long strideA, long long strideB, long long strideC)
{
#if HAS_TCGEN05
    extern __shared__ char smem[];
    const u32 smem_base = smem_u32(smem);
    const u32 tiles_addr = (smem_base + 1024 + 1023) & ~1023u;

    const int tid = threadIdx.x;
    const int wid = tid >> 5;
    const int lid = tid & 31;

    const int b = blockIdx.z;
    A  += (long long)b * strideA;
    BT += (long long)b * strideB;
    C  += (long long)b * strideC;

    const int row0 = blockIdx.y * TM_TILE;
    const int col0 = blockIdx.x * TN_TILE;

    const u32 mbar0 = smem_base + 8;       // STAGES slot barriers
    const u32 mbarF = smem_base + 8 + 8 * STAGES;

    if (tid == 0) {
        #pragma unroll
        for (int s = 0; s < STAGES; s++) mbar_init(mbar0 + 8 * s, 1);
        mbar_init(mbarF, 1);
    }
    if (wid == 0) {
        tmem_alloc(smem_base + 0, 512);
        tmem_relinquish();
    }
    __syncthreads();
    u32 tmem;
    asm volatile("ld.shared.b32 %0, [%1];" : "=r"(tmem) : "r"(smem_base + 0));

    const int c16   = tid & 7;      // 16B chunk within 128B row
    const int rbase = tid >> 3;     // 0..15

    const float* Abase = A  + (long long)(row0 + rbase) * lda  + c16 * 4;
    const float* Bbase = BT + (long long)(col0 + rbase) * ldbt + c16 * 4;

    const int KT = K / TK;
    u32 phases = 0;

    auto load_tile = [&](int kt) {
        const int slot = kt % STAGES;
        const u32 At = tiles_addr + slot * STAGE_BYTES;
        const u32 Bt = At + A_BYTES;
        const float* as = Abase + kt * TK;
        const float* bs = Bbase + kt * TK;
        #pragma unroll
        for (int p = 0; p < 16; p++) {      // A: 256 rows
            const int r = rbase + p * 16;
            cp_async16(At + SW128((u32)(r * 128 + c16 * 16)),
                       as + (long long)(p * 16) * lda);
        }
        #pragma unroll
        for (int p = 0; p < 16; p++) {      // B: 256 rows
            const int r = rbase + p * 16;
            cp_async16(Bt + SW128((u32)(r * 128 + c16 * 16)),
                       bs + (long long)(p * 16) * ldbt);
        }
        cp_commit();
    };

    #pragma unroll
    for (int t = 0; t < PRELOAD; t++) load_tile(t);

    for (int i = 0; i < KT; i++) {
        // commits so far = PRELOAD + i ; pending <= 1 => tile i landed
        cp_wait1();
        fence_async_proxy();
        __syncthreads();

        if (wid == 0 && elect1()) {
            const int slot = i % STAGES;
            const u32 At = tiles_addr + slot * STAGE_BYTES;
            const u64 a0 = mk_desc(At);                       // A rows 0..127
            const u64 a1 = mk_desc(At + 16384);               // A rows 128..255
            const u64 b0 = mk_desc(At + A_BYTES);             // B rows 0..127
            const u64 b1 = mk_desc(At + A_BYTES + 16384);     // B rows 128..255
            #pragma unroll
            for (int sub = 0; sub < 4; sub++) {
                const u32 en = (i | sub) != 0;
                const u64 o = sub * 2;
                mma_tf32_ss(tmem,       a0 + o, b0 + o, IDESC_TF32, en);
                mma_tf32_ss(tmem + 128, a0 + o, b1 + o, IDESC_TF32, en);
                mma_tf32_ss(tmem + 256, a1 + o, b0 + o, IDESC_TF32, en);
                mma_tf32_ss(tmem + 384, a1 + o, b1 + o, IDESC_TF32, en);
            }
            mma_commit(mbar0 + 8 * slot);
        }

        const int j = i + PRELOAD;
        if (j < KT) {
            // slot j%STAGES previously held tile j-STAGES = i-1
            if (i >= 1) {
                const int s = (i - 1) % STAGES;
                mbar_wait(mbar0 + 8 * s, (phases >> s) & 1);
                phases ^= (1u << s);
            }
            load_tile(j);
        } else {
            cp_commit();   // empty group keeps wait_group accounting exact
        }
    }

    if (wid == 0 && elect1()) mma_commit(mbarF);
    mbar_wait(mbarF, 0);
    tc_fence_after();

    // epilogue: 2 row blocks; warp w -> lanes w*32..w*32+31 of each block
    #pragma unroll
    for (int blk = 0; blk < 2; blk++) {
        const int grow = row0 + blk * 128 + wid * 32 + lid;
        float* crow = C + (long long)grow * ldc + col0;
        #pragma unroll
        for (int cb = 0; cb < 8; cb++) {
            u32 r[32];
            tmem_ld32(r, tmem + blk * 256 + cb * 32);
            tmem_wait_ld();
            #pragma unroll
            for (int jj = 0; jj < 32; jj += 4) {
                float4 t;
                t.x = alpha * __uint_as_float(r[jj + 0]);
                t.y = alpha * __uint_as_float(r[jj + 1]);
                t.z = alpha * __uint_as_float(r[jj + 2]);
                t.w = alpha * __uint_as_float(r[jj + 3]);
                *(float4*)(crow + cb * 32 + jj) = t;
            }
        }
    }

    __syncthreads();
    if (wid == 0) tmem_dealloc(tmem, 512);
#endif  // HAS_TCGEN05
}

// ---------------------------------------------------------------------------
__global__ __launch_bounds__(256) void round_tf32_vec(
    const float* __restrict__ src, float* __restrict__ dst)
{
    const long long i = ((long long)blockIdx.x * 256 + threadIdx.x) * 4;
    float4 t = *(const float4*)(src + i);
    uint4 u;
    u.x = cvt_tf32(t.x); u.y = cvt_tf32(t.y);
    u.z = cvt_tf32(t.z); u.w = cvt_tf32(t.w);
    *(uint4*)(dst + i) = u;
}

__global__ __launch_bounds__(256) void transpose_round(
    const float* __restrict__ src, float* __restrict__ dst, int R, int C)
{
    __shared__ float t[32][33];
    const long long boff = (long long)blockIdx.z * R * C;
    src += boff; dst += boff;
    const int r0 = blockIdx.y * 32, c0 = blockIdx.x * 32;
    const int tx = threadIdx.x, ty = threadIdx.y;   // (32, 8)
    #pragma unroll
    for (int i = 0; i < 4; i++)
        t[ty + 8 * i][tx] = src[(long long)(r0 + ty + 8 * i) * C + c0 + tx];
    __syncthreads();
    #pragma unroll
    for (int i = 0; i < 4; i++)
        dst[(long long)(c0 + ty + 8 * i) * R + r0 + tx] =
            __uint_as_float(cvt_tf32(t[tx][ty + 8 * i]));
}

__global__ __launch_bounds__(256) void softmax_rows(float* __restrict__ scores)
{
    const long long row = blockIdx.x;
    float* p = scores + row * (long long)ATT_S;
    const int tid = threadIdx.x;

    float v[8];
    float m = -CUDART_INF_F;
    #pragma unroll
    for (int i = 0; i < 8; i++) {
        v[i] = p[tid + i * 256];
        m = fmaxf(m, v[i]);
    }
    __shared__ float red[8];
    #pragma unroll
    for (int o = 16; o > 0; o >>= 1)
        m = fmaxf(m, __shfl_xor_sync(0xffffffffu, m, o));
    if ((tid & 31) == 0) red[tid >> 5] = m;
    __syncthreads();
    float bm = red[0];
    #pragma unroll
    for (int i = 1; i < 8; i++) bm = fmaxf(bm, red[i]);
    __syncthreads();

    float s = 0.0f;
    #pragma unroll
    for (int i = 0; i < 8; i++) {
        v[i] = __expf(v[i] - bm);
        s += v[i];
    }
    #pragma unroll
    for (int o = 16; o > 0; o >>= 1)
        s += __shfl_xor_sync(0xffffffffu, s, o);
    if ((tid & 31) == 0) red[tid >> 5] = s;
    __syncthreads();
    float total = 0.0f;
    #pragma unroll
    for (int i = 0; i < 8; i++) total += red[i];

    float inv = 1.0f / total;
    #pragma unroll
    for (int i = 0; i < 8; i++)
        p[tid + i * 256] = __uint_as_float(cvt_tf32(v[i] * inv));
}

// ---------------------------------------------------------------------------
extern "C" void kernel_launch(void* const* d_in, const int* in_sizes, int n_in,
                              void* d_out, int out_size)
{
    const float* q = (const float*)d_in[0];   // [B, S, D]
    const float* k = (const float*)d_in[1];   // [B, D, S]
    const float* v = (const float*)d_in[2];   // [B, S, Dv]
    float* out = (float*)d_out;               // [B, S, Dv]

    float *scores, *qr, *kT, *vT;
    cudaGetSymbolAddress((void**)&scores, g_scores);
    cudaGetSymbolAddress((void**)&qr, g_qr);
    cudaGetSymbolAddress((void**)&kT, g_kT);
    cudaGetSymbolAddress((void**)&vT, g_vT);

    const int B = ATT_B, S = ATT_S, D = ATT_D;

    cudaFuncSetAttribute(gemm_tf32_pipe,
                         cudaFuncAttributeMaxDynamicSharedMemorySize, SMEM_DYN);

    {
        long long nq = (long long)B * S * D;
        round_tf32_vec<<<(unsigned)(nq / (256 * 4)), 256>>>(q, qr);
        dim3 blk(32, 8);
        transpose_round<<<dim3(S / 32, D / 32, B), blk>>>(k, kT, D, S);
        transpose_round<<<dim3(D / 32, S / 32, B), blk>>>(v, vT, S, D);
    }

    {   // scores = 0.1 * qr @ kT^T : M=S, N=S, K=D
        dim3 grid(S / TN_TILE, S / TM_TILE, B);
        gemm_tf32_pipe<<<grid, 128, SMEM_DYN>>>(qr, kT, scores,
                                                D, D, D, S, 0.1f,
                                                (long long)S * D, (long long)S * D,
                                                (long long)S * S);
    }
    {
        softmax_rows<<<B * S, 256>>>(scores);
    }
    {   // out = scores @ vT^T : M=S, N=D, K=S
        dim3 grid(D / TN_TILE, S / TM_TILE, B);
        gemm_tf32_pipe<<<grid, 128, SMEM_DYN>>>(scores, vT, out,
                                                S, S, S, D, 1.0f,
                                                (long long)S * S, (long long)D * S,
                                                (long long)S * D);
    }
}